// round 2
// baseline (speedup 1.0000x reference)
#include <cuda_runtime.h>
#include <math.h>

// Problem-fixed sizes: N_TRAIN=131072, M_TEST=65536, T=196608
#define TMAXN 196608
#define WARM  8192
#define CHUNK 16

// Merged per-step input: (t, residual, R, is_obs)
__device__ float4 g_in[TMAXN];
// Test index per merged position (-1 for train points)
__device__ int    g_tj[TMAXN];
// Filter record per step: 5 float4:
//  r0 = (mp0, mp1, mp2, Pp00)
//  r1 = (Pp01, Pp02, Pp11, Pp12)
//  r2 = (Pp22, mf0, mf1, mf2)
//  r3 = (Pf00, Pf01, Pf02, Pf11)
//  r4 = (Pf12, Pf22, dt, 0)
__device__ float4 g_rec[(size_t)TMAXN * 5];

__global__ void merge_kernel(const float* __restrict__ times, const float* __restrict__ tstar,
                             const float* __restrict__ n1, const float* __restrict__ n2,
                             const float* __restrict__ pmc, int N, int M) {
    int i = blockIdx.x * blockDim.x + threadIdx.x;
    if (i < N) {
        float x = times[i];
        // stable argsort on concat([times, tstar]): equal keys keep train first.
        // position = i + #{ tstar < x }  (lower_bound)
        int lo = 0, hi = M;
        while (lo < hi) { int mid = (lo + hi) >> 1; if (tstar[mid] < x) lo = mid + 1; else hi = mid; }
        int p = i + lo;
        float s2 = n2[i];
        float mc = *pmc;
        g_in[p] = make_float4(x, n1[i] / s2 - mc, 1.0f / s2, 1.0f);
        g_tj[p] = -1;
    } else if (i < N + M) {
        int j = i - N;
        float x = tstar[j];
        // position = j + #{ times <= x }  (upper_bound)
        int lo = 0, hi = N;
        while (lo < hi) { int mid = (lo + hi) >> 1; if (times[mid] <= x) lo = mid + 1; else hi = mid; }
        int p = j + lo;
        g_in[p] = make_float4(x, 0.0f, 1.0f, 0.0f);
        g_tj[p] = j;
    }
}

// A(dt) = exp(-lam*dt) * (I + dt*Nm + 0.5*dt^2*Nm^2), Nm nilpotent (Nm^3 = 0)
// Nm   = [[lam, 1, 0], [0, lam, 1], [-lam^3, -3lam^2, -2lam]]
// Nm^2 = [[lam^2, 2lam, 1], [-lam^3, -2lam^2, -lam], [lam^4, 2lam^3, lam^2]]
#define COMPUTE_A(dt)                                              \
    float ed = __expf(-lam * (dt));                                \
    float d2 = 0.5f * (dt) * (dt);                                 \
    float A00 = ed * (1.0f + (dt) * lam + d2 * lam2);              \
    float A01 = ed * ((dt) + d2 * (2.0f * lam));                   \
    float A02 = ed * d2;                                           \
    float A10 = ed * (-d2 * lam3);                                 \
    float A11 = ed * (1.0f + (dt) * lam - d2 * (2.0f * lam2));     \
    float A12 = ed * ((dt) - d2 * lam);                            \
    float A20 = ed * (-(dt) * lam3 + d2 * lam4);                   \
    float A21 = ed * (-3.0f * (dt) * lam2 + d2 * (2.0f * lam3));   \
    float A22 = ed * (1.0f - 2.0f * (dt) * lam + d2 * lam2);

__global__ void forward_kernel(const float* __restrict__ pvar, const float* __restrict__ pls, int T) {
    int c = blockIdx.x * blockDim.x + threadIdx.x;
    int nchunks = (T + CHUNK - 1) / CHUNK;
    if (c >= nchunks) return;
    int s  = c * CHUNK;
    int e  = min(T, s + CHUNK);
    int w0 = max(0, s - WARM);

    float var = *pvar;
    float lam = sqrtf(5.0f) / (*pls);
    float lam2 = lam * lam, lam3 = lam2 * lam, lam4 = lam2 * lam2;
    float kap = lam2 * (1.0f / 3.0f);
    float pi00 = var, pi02 = -var * kap, pi11 = var * kap, pi22 = var * lam4;

    float m0 = 0.f, m1 = 0.f, m2 = 0.f;
    float P00 = pi00, P01 = 0.f, P02 = pi02, P11 = pi11, P12 = 0.f, P22 = pi22;
    float tprev = (w0 > 0) ? g_in[w0 - 1].x : 0.0f;

    for (int k = w0; k < e; ++k) {
        float4 in = g_in[k];
        float dt = (k == 0) ? 0.0f : (in.x - tprev);
        tprev = in.x;
        float r = in.y, R = in.z, obs = in.w;

        COMPUTE_A(dt);

        // Q = Pinf - A Pinf A^T   (Pinf = [[pi00,0,pi02],[0,pi11,0],[pi02,0,pi22]])
        float B00 = A00 * pi00 + A02 * pi02, B01 = A01 * pi11, B02 = A00 * pi02 + A02 * pi22;
        float B10 = A10 * pi00 + A12 * pi02, B11 = A11 * pi11, B12 = A10 * pi02 + A12 * pi22;
        float B20 = A20 * pi00 + A22 * pi02, B21 = A21 * pi11, B22 = A20 * pi02 + A22 * pi22;
        float Q00 = pi00 - (B00 * A00 + B01 * A01 + B02 * A02);
        float Q01 =       - (B00 * A10 + B01 * A11 + B02 * A12);
        float Q02 = pi02 - (B00 * A20 + B01 * A21 + B02 * A22);
        float Q11 = pi11 - (B10 * A10 + B11 * A11 + B12 * A12);
        float Q12 =       - (B10 * A20 + B11 * A21 + B12 * A22);
        float Q22 = pi22 - (B20 * A20 + B21 * A21 + B22 * A22);

        // P_pred = A P A^T + Q
        float C00 = A00 * P00 + A01 * P01 + A02 * P02;
        float C01 = A00 * P01 + A01 * P11 + A02 * P12;
        float C02 = A00 * P02 + A01 * P12 + A02 * P22;
        float C10 = A10 * P00 + A11 * P01 + A12 * P02;
        float C11 = A10 * P01 + A11 * P11 + A12 * P12;
        float C12 = A10 * P02 + A11 * P12 + A12 * P22;
        float C20 = A20 * P00 + A21 * P01 + A22 * P02;
        float C21 = A20 * P01 + A21 * P11 + A22 * P12;
        float C22 = A20 * P02 + A21 * P12 + A22 * P22;
        float Pp00 = C00 * A00 + C01 * A01 + C02 * A02 + Q00;
        float Pp01 = C00 * A10 + C01 * A11 + C02 * A12 + Q01;
        float Pp02 = C00 * A20 + C01 * A21 + C02 * A22 + Q02;
        float Pp11 = C10 * A10 + C11 * A11 + C12 * A12 + Q11;
        float Pp12 = C10 * A20 + C11 * A21 + C12 * A22 + Q12;
        float Pp22 = C20 * A20 + C21 * A21 + C22 * A22 + Q22;

        float mp0 = A00 * m0 + A01 * m1 + A02 * m2;
        float mp1 = A10 * m0 + A11 * m1 + A12 * m2;
        float mp2 = A20 * m0 + A21 * m1 + A22 * m2;

        // Update (K = obs * Ppred h / S)
        float S  = Pp00 + R;
        float iS = obs / S;
        float K0 = Pp00 * iS, K1 = Pp01 * iS, K2 = Pp02 * iS;
        float v = r - mp0;
        m0 = mp0 + K0 * v; m1 = mp1 + K1 * v; m2 = mp2 + K2 * v;
        P00 = Pp00 - K0 * K0 * S;
        P01 = Pp01 - K0 * K1 * S;
        P02 = Pp02 - K0 * K2 * S;
        P11 = Pp11 - K1 * K1 * S;
        P12 = Pp12 - K1 * K2 * S;
        P22 = Pp22 - K2 * K2 * S;

        if (k >= s) {
            size_t b = (size_t)k * 5;
            g_rec[b + 0] = make_float4(mp0, mp1, mp2, Pp00);
            g_rec[b + 1] = make_float4(Pp01, Pp02, Pp11, Pp12);
            g_rec[b + 2] = make_float4(Pp22, m0, m1, m2);
            g_rec[b + 3] = make_float4(P00, P01, P02, P11);
            g_rec[b + 4] = make_float4(P12, P22, dt, 0.0f);
        }
    }
}

__global__ void backward_kernel(const float* __restrict__ pls, const float* __restrict__ pmc,
                                float* __restrict__ out, int T, int M) {
    int c = blockIdx.x * blockDim.x + threadIdx.x;
    int nchunks = (T + CHUNK - 1) / CHUNK;
    if (c >= nchunks) return;
    int s = c * CHUNK;
    int e = min(T, s + CHUNK);

    float mc  = *pmc;
    float lam = sqrtf(5.0f) / (*pls);
    float lam2 = lam * lam, lam3 = lam2 * lam, lam4 = lam2 * lam2;

    // Smoothed carry at index (k+1), and pred-side data of index (k+1)
    float ms0, ms1, ms2, Ps00, Ps01, Ps02, Ps11, Ps12, Ps22;
    float mpn0, mpn1, mpn2, Ppn00, Ppn01, Ppn02, Ppn11, Ppn12, Ppn22, dtn;
    int kstart;
    {
        int kinit = (e == T) ? (T - 1) : min(T - 1, e - 1 + WARM);
        size_t b = (size_t)kinit * 5;
        float4 r0 = g_rec[b], r1 = g_rec[b + 1], r2 = g_rec[b + 2], r3 = g_rec[b + 3], r4 = g_rec[b + 4];
        // init carry with filtered state (exact if kinit == T-1, else decays over warm-up)
        ms0 = r2.y; ms1 = r2.z; ms2 = r2.w;
        Ps00 = r3.x; Ps01 = r3.y; Ps02 = r3.z; Ps11 = r3.w; Ps12 = r4.x; Ps22 = r4.y;
        mpn0 = r0.x; mpn1 = r0.y; mpn2 = r0.z;
        Ppn00 = r0.w; Ppn01 = r1.x; Ppn02 = r1.y; Ppn11 = r1.z; Ppn12 = r1.w; Ppn22 = r2.x;
        dtn = r4.z;
        if (kinit == T - 1 && kinit < e) {  // only the chunk owning T-1 writes it
            int tj = g_tj[kinit];
            if (tj >= 0) { out[tj] = ms0 + mc; out[M + tj] = fmaxf(Ps00, 0.0f); }
        }
        kstart = kinit - 1;
    }

    for (int k = kstart; k >= s; --k) {
        size_t b = (size_t)k * 5;
        float4 r0 = g_rec[b], r1 = g_rec[b + 1], r2 = g_rec[b + 2], r3 = g_rec[b + 3], r4 = g_rec[b + 4];
        float mf0 = r2.y, mf1 = r2.z, mf2 = r2.w;
        float Pf00 = r3.x, Pf01 = r3.y, Pf02 = r3.z, Pf11 = r3.w, Pf12 = r4.x, Pf22 = r4.y;

        COMPUTE_A(dtn);  // A_{k+1}

        // Pi = inv(P_pred_{k+1})  (symmetric, adjugate)
        float c00 = Ppn11 * Ppn22 - Ppn12 * Ppn12;
        float c01 = Ppn02 * Ppn12 - Ppn01 * Ppn22;
        float c02 = Ppn01 * Ppn12 - Ppn02 * Ppn11;
        float c11 = Ppn00 * Ppn22 - Ppn02 * Ppn02;
        float c12 = Ppn01 * Ppn02 - Ppn00 * Ppn12;
        float c22 = Ppn00 * Ppn11 - Ppn01 * Ppn01;
        float det  = Ppn00 * c00 + Ppn01 * c01 + Ppn02 * c02;
        float idet = 1.0f / det;
        float I00 = c00 * idet, I01 = c01 * idet, I02 = c02 * idet;
        float I11 = c11 * idet, I12 = c12 * idet, I22 = c22 * idet;

        // U = A^T * Pi
        float U00 = A00 * I00 + A10 * I01 + A20 * I02;
        float U01 = A00 * I01 + A10 * I11 + A20 * I12;
        float U02 = A00 * I02 + A10 * I12 + A20 * I22;
        float U10 = A01 * I00 + A11 * I01 + A21 * I02;
        float U11 = A01 * I01 + A11 * I11 + A21 * I12;
        float U12 = A01 * I02 + A11 * I12 + A21 * I22;
        float U20 = A02 * I00 + A12 * I01 + A22 * I02;
        float U21 = A02 * I01 + A12 * I11 + A22 * I12;
        float U22 = A02 * I02 + A12 * I12 + A22 * I22;

        // G = Pf * U   (Pf symmetric)
        float G00 = Pf00 * U00 + Pf01 * U10 + Pf02 * U20;
        float G01 = Pf00 * U01 + Pf01 * U11 + Pf02 * U21;
        float G02 = Pf00 * U02 + Pf01 * U12 + Pf02 * U22;
        float G10 = Pf01 * U00 + Pf11 * U10 + Pf12 * U20;
        float G11 = Pf01 * U01 + Pf11 * U11 + Pf12 * U21;
        float G12 = Pf01 * U02 + Pf11 * U12 + Pf12 * U22;
        float G20 = Pf02 * U00 + Pf12 * U10 + Pf22 * U20;
        float G21 = Pf02 * U01 + Pf12 * U11 + Pf22 * U21;
        float G22 = Pf02 * U02 + Pf12 * U12 + Pf22 * U22;

        // m_s = m_f + G (m_s_next - m_pred_next)
        float dm0 = ms0 - mpn0, dm1 = ms1 - mpn1, dm2 = ms2 - mpn2;
        float nm0 = mf0 + G00 * dm0 + G01 * dm1 + G02 * dm2;
        float nm1 = mf1 + G10 * dm0 + G11 * dm1 + G12 * dm2;
        float nm2 = mf2 + G20 * dm0 + G21 * dm1 + G22 * dm2;

        // P_s = P_f + G (P_s_next - P_pred_next) G^T
        float D00 = Ps00 - Ppn00, D01 = Ps01 - Ppn01, D02 = Ps02 - Ppn02;
        float D11 = Ps11 - Ppn11, D12 = Ps12 - Ppn12, D22 = Ps22 - Ppn22;
        float T00 = G00 * D00 + G01 * D01 + G02 * D02;
        float T01 = G00 * D01 + G01 * D11 + G02 * D12;
        float T02 = G00 * D02 + G01 * D12 + G02 * D22;
        float T10 = G10 * D00 + G11 * D01 + G12 * D02;
        float T11 = G10 * D01 + G11 * D11 + G12 * D12;
        float T12 = G10 * D02 + G11 * D12 + G12 * D22;
        float T20 = G20 * D00 + G21 * D01 + G22 * D02;
        float T21 = G20 * D01 + G21 * D11 + G22 * D12;
        float T22 = G20 * D02 + G21 * D12 + G22 * D22;
        float nP00 = Pf00 + T00 * G00 + T01 * G01 + T02 * G02;
        float nP01 = Pf01 + T00 * G10 + T01 * G11 + T02 * G12;
        float nP02 = Pf02 + T00 * G20 + T01 * G21 + T02 * G22;
        float nP11 = Pf11 + T10 * G10 + T11 * G11 + T12 * G12;
        float nP12 = Pf12 + T10 * G20 + T11 * G21 + T12 * G22;
        float nP22 = Pf22 + T20 * G20 + T21 * G21 + T22 * G22;

        ms0 = nm0; ms1 = nm1; ms2 = nm2;
        Ps00 = nP00; Ps01 = nP01; Ps02 = nP02; Ps11 = nP11; Ps12 = nP12; Ps22 = nP22;

        if (k < e) {  // payload only (warm-up iterations have k >= e)
            int tj = g_tj[k];
            if (tj >= 0) { out[tj] = ms0 + mc; out[M + tj] = fmaxf(Ps00, 0.0f); }
        }

        // current record becomes "next" for k-1
        mpn0 = r0.x; mpn1 = r0.y; mpn2 = r0.z;
        Ppn00 = r0.w; Ppn01 = r1.x; Ppn02 = r1.y; Ppn11 = r1.z; Ppn12 = r1.w; Ppn22 = r2.x;
        dtn = r4.z;
    }
}

extern "C" void kernel_launch(void* const* d_in, const int* in_sizes, int n_in,
                              void* d_out, int out_size) {
    const float* times = (const float*)d_in[0];
    const float* tstar = (const float*)d_in[1];
    const float* n1    = (const float*)d_in[2];
    const float* n2    = (const float*)d_in[3];
    const float* pvar  = (const float*)d_in[4];
    const float* pls   = (const float*)d_in[5];
    const float* pmc   = (const float*)d_in[6];
    int N = in_sizes[0];
    int M = in_sizes[1];
    int T = N + M;

    int total = N + M;
    merge_kernel<<<(total + 255) / 256, 256>>>(times, tstar, n1, n2, pmc, N, M);

    int nchunks = (T + CHUNK - 1) / CHUNK;
    int bs = 64;
    int nb = (nchunks + bs - 1) / bs;
    forward_kernel<<<nb, bs>>>(pvar, pls, T);
    backward_kernel<<<nb, bs>>>(pls, pmc, (float*)d_out, T, M);
}

// round 6
// speedup vs baseline: 1.8580x; 1.8580x over previous
#include <cuda_runtime.h>
#include <math.h>

// Problem-fixed: N_TRAIN=131072, M_TEST=65536
#define TT     196608
#define LOGC   6
#define CHUNK  64
#define NCH    (TT / CHUNK)   // 3072
#define WARM   6144

// Transposed merged inputs: index (j, chunk) -> j*NCH + chunk. (t, residual, R, is_obs)
__device__ float4 g_in_t[(size_t)CHUNK * NCH];
__device__ int    g_tj[TT];
// Filter record, SoA-transposed: field f of slot k at ((f*CHUNK + j)*NCH + c), c=k>>6, j=k&63
//  F0=(mf0,mf1,mf2,mp0)  F1=(mp1,mp2,Pp00,Pp01)  F2=(Pp02,Pp11,Pp12,Pp22)
//  F3=(Pf00,Pf01,Pf02,Pf11)  F4=(Pf12,Pf22,G22,-)  F5=(G00,G01,G02,G10)  F6=(G11,G12,G20,G21)
// F4.xy written by slot owner; F4.z (G22) written by owner of slot+1. Disjoint addresses.
__device__ float4 g_rec[(size_t)7 * CHUNK * NCH];

__device__ __forceinline__ size_t ridx(int f, int slot) {
    int c = slot >> LOGC, j = slot & (CHUNK - 1);
    return ((size_t)(f * CHUNK + j)) * NCH + c;
}

__global__ void merge_kernel(const float* __restrict__ times, const float* __restrict__ tstar,
                             const float* __restrict__ n1, const float* __restrict__ n2,
                             const float* __restrict__ pmc, int N, int M) {
    int i = blockIdx.x * blockDim.x + threadIdx.x;
    if (i < N) {
        float x = times[i];
        // stable argsort: equal keys keep train first -> position = i + #{tstar < x}
        int lo = 0, hi = M;
        while (lo < hi) { int mid = (lo + hi) >> 1; if (tstar[mid] < x) lo = mid + 1; else hi = mid; }
        int p = i + lo;
        float s2 = n2[i];
        float mc = *pmc;
        g_in_t[(size_t)(p & (CHUNK - 1)) * NCH + (p >> LOGC)] =
            make_float4(x, n1[i] / s2 - mc, 1.0f / s2, 1.0f);
        g_tj[p] = -1;
    } else if (i < N + M) {
        int j = i - N;
        float x = tstar[j];
        // position = j + #{times <= x}
        int lo = 0, hi = N;
        while (lo < hi) { int mid = (lo + hi) >> 1; if (times[mid] <= x) lo = mid + 1; else hi = mid; }
        int p = j + lo;
        g_in_t[(size_t)(p & (CHUNK - 1)) * NCH + (p >> LOGC)] = make_float4(x, 0.0f, 1.0f, 0.0f);
        g_tj[p] = j;
    }
}

// A(dt) = exp(-lam*dt) * (I + dt*Nm + 0.5 dt^2 Nm^2), Nm nilpotent
#define COMPUTE_A(dt)                                              \
    float ed = __expf(-lam * (dt));                                \
    float d2 = 0.5f * (dt) * (dt);                                 \
    float A00 = ed * (1.0f + (dt) * lam + d2 * lam2);              \
    float A01 = ed * ((dt) + d2 * (2.0f * lam));                   \
    float A02 = ed * d2;                                           \
    float A10 = ed * (-d2 * lam3);                                 \
    float A11 = ed * (1.0f + (dt) * lam - d2 * (2.0f * lam2));     \
    float A12 = ed * ((dt) - d2 * lam);                            \
    float A20 = ed * (-(dt) * lam3 + d2 * lam4);                   \
    float A21 = ed * (-3.0f * (dt) * lam2 + d2 * (2.0f * lam3));   \
    float A22 = ed * (1.0f - 2.0f * (dt) * lam + d2 * lam2);

__global__ void forward_kernel(const float* __restrict__ pvar, const float* __restrict__ pls) {
    int c = blockIdx.x * blockDim.x + threadIdx.x;
    if (c >= NCH) return;
    int s = c * CHUNK, e = s + CHUNK;
    int k0 = max(0, s - WARM);

    float var = *pvar;
    float lam = sqrtf(5.0f) / (*pls);
    float lam2 = lam * lam, lam3 = lam2 * lam, lam4 = lam2 * lam2;
    float kap = lam2 * (1.0f / 3.0f);
    float pi00 = var, pi02 = -var * kap, pi11 = var * kap, pi22 = var * lam4;

    float m0 = 0.f, m1 = 0.f, m2 = 0.f;
    float P00 = pi00, P01 = 0.f, P02 = pi02, P11 = pi11, P12 = 0.f, P22 = pi22;
    float tprev = 0.0f;
    if (k0 > 0) tprev = g_in_t[(size_t)((k0 - 1) & (CHUNK - 1)) * NCH + ((k0 - 1) >> LOGC)].x;

    float4 in = g_in_t[(size_t)(k0 & (CHUNK - 1)) * NCH + (k0 >> LOGC)];

    for (int k = k0; k < e; ++k) {
        float4 nin = in;
        if (k + 1 < e)  // prefetch next step's input
            nin = g_in_t[(size_t)((k + 1) & (CHUNK - 1)) * NCH + ((k + 1) >> LOGC)];

        float dt = (k == 0) ? 0.0f : (in.x - tprev);
        tprev = in.x;
        float r = in.y, R = in.z, obs = in.w;

        COMPUTE_A(dt);

        // Delta = P_filt(k-1) - Pinf  (Pinf has zeros at 01,12)
        float D00 = P00 - pi00, D01 = P01, D02 = P02 - pi02;
        float D11 = P11 - pi11, D12 = P12, D22 = P22 - pi22;
        // C = A * Delta
        float C00 = A00 * D00 + A01 * D01 + A02 * D02;
        float C01 = A00 * D01 + A01 * D11 + A02 * D12;
        float C02 = A00 * D02 + A01 * D12 + A02 * D22;
        float C10 = A10 * D00 + A11 * D01 + A12 * D02;
        float C11 = A10 * D01 + A11 * D11 + A12 * D12;
        float C12 = A10 * D02 + A11 * D12 + A12 * D22;
        float C20 = A20 * D00 + A21 * D01 + A22 * D02;
        float C21 = A20 * D01 + A21 * D11 + A22 * D12;
        float C22 = A20 * D02 + A21 * D12 + A22 * D22;
        // P_pred = C A^T + Pinf   (== A P A^T + Q, exact identity)
        float Pp00 = C00 * A00 + C01 * A01 + C02 * A02 + pi00;
        float Pp01 = C00 * A10 + C01 * A11 + C02 * A12;
        float Pp02 = C00 * A20 + C01 * A21 + C02 * A22 + pi02;
        float Pp11 = C10 * A10 + C11 * A11 + C12 * A12 + pi11;
        float Pp12 = C10 * A20 + C11 * A21 + C12 * A22;
        float Pp22 = C20 * A20 + C21 * A21 + C22 * A22 + pi22;

        float mp0 = A00 * m0 + A01 * m1 + A02 * m2;
        float mp1 = A10 * m0 + A11 * m1 + A12 * m2;
        float mp2 = A20 * m0 + A21 * m1 + A22 * m2;

        // Smoother gain for slot k-1: G = P_filt(k-1) A^T Ppred^{-1} = (A P_filt)^T Inv
        if (k >= s && k > 0) {
            float AP00 = C00 + A00 * pi00 + A02 * pi02;
            float AP01 = C01 + A01 * pi11;
            float AP02 = C02 + A00 * pi02 + A02 * pi22;
            float AP10 = C10 + A10 * pi00 + A12 * pi02;
            float AP11 = C11 + A11 * pi11;
            float AP12 = C12 + A10 * pi02 + A12 * pi22;
            float AP20 = C20 + A20 * pi00 + A22 * pi02;
            float AP21 = C21 + A21 * pi11;
            float AP22 = C22 + A20 * pi02 + A22 * pi22;

            float i00 = Pp11 * Pp22 - Pp12 * Pp12;
            float i01 = Pp02 * Pp12 - Pp01 * Pp22;
            float i02 = Pp01 * Pp12 - Pp02 * Pp11;
            float i11 = Pp00 * Pp22 - Pp02 * Pp02;
            float i12 = Pp01 * Pp02 - Pp00 * Pp12;
            float i22 = Pp00 * Pp11 - Pp01 * Pp01;
            float det = Pp00 * i00 + Pp01 * i01 + Pp02 * i02;
            float idet = 1.0f / det;
            i00 *= idet; i01 *= idet; i02 *= idet; i11 *= idet; i12 *= idet; i22 *= idet;

            float G00 = AP00 * i00 + AP10 * i01 + AP20 * i02;
            float G01 = AP00 * i01 + AP10 * i11 + AP20 * i12;
            float G02 = AP00 * i02 + AP10 * i12 + AP20 * i22;
            float G10 = AP01 * i00 + AP11 * i01 + AP21 * i02;
            float G11 = AP01 * i01 + AP11 * i11 + AP21 * i12;
            float G12 = AP01 * i02 + AP11 * i12 + AP21 * i22;
            float G20 = AP02 * i00 + AP12 * i01 + AP22 * i02;
            float G21 = AP02 * i01 + AP12 * i11 + AP22 * i12;
            float G22 = AP02 * i02 + AP12 * i12 + AP22 * i22;

            int q = k - 1;
            g_rec[ridx(5, q)] = make_float4(G00, G01, G02, G10);
            g_rec[ridx(6, q)] = make_float4(G11, G12, G20, G21);
            ((float*)&g_rec[ridx(4, q)])[2] = G22;
        }

        // Measurement update
        float S = Pp00 + R;
        float iS = obs / S;
        float K0 = Pp00 * iS, K1 = Pp01 * iS, K2 = Pp02 * iS;
        float v = r - mp0;
        m0 = mp0 + K0 * v; m1 = mp1 + K1 * v; m2 = mp2 + K2 * v;
        P00 = Pp00 - K0 * K0 * S;
        P01 = Pp01 - K0 * K1 * S;
        P02 = Pp02 - K0 * K2 * S;
        P11 = Pp11 - K1 * K1 * S;
        P12 = Pp12 - K1 * K2 * S;
        P22 = Pp22 - K2 * K2 * S;

        if (k >= s) {
            g_rec[ridx(0, k)] = make_float4(m0, m1, m2, mp0);
            g_rec[ridx(1, k)] = make_float4(mp1, mp2, Pp00, Pp01);
            g_rec[ridx(2, k)] = make_float4(Pp02, Pp11, Pp12, Pp22);
            g_rec[ridx(3, k)] = make_float4(P00, P01, P02, P11);
            float* f4 = (float*)&g_rec[ridx(4, k)];
            f4[0] = P12; f4[1] = P22;
        }
        in = nin;
    }
}

__global__ void backward_kernel(const float* __restrict__ pmc, float* __restrict__ out, int M) {
    int c = blockIdx.x * blockDim.x + threadIdx.x;
    if (c >= NCH) return;
    int s = c * CHUNK, e = s + CHUNK;
    float mc = *pmc;

    int kinit = min(TT - 1, e - 1 + WARM);

    float ms0, ms1, ms2, Ps00, Ps01, Ps02, Ps11, Ps12, Ps22;
    float mpn0, mpn1, mpn2, Ppn00, Ppn01, Ppn02, Ppn11, Ppn12, Ppn22;
    {
        float4 r0 = g_rec[ridx(0, kinit)], r1 = g_rec[ridx(1, kinit)];
        float4 r2 = g_rec[ridx(2, kinit)], r3 = g_rec[ridx(3, kinit)];
        float4 r4 = g_rec[ridx(4, kinit)];
        ms0 = r0.x; ms1 = r0.y; ms2 = r0.z;          // init carry = filtered state
        Ps00 = r3.x; Ps01 = r3.y; Ps02 = r3.z; Ps11 = r3.w; Ps12 = r4.x; Ps22 = r4.y;
        mpn0 = r0.w; mpn1 = r1.x; mpn2 = r1.y;
        Ppn00 = r1.z; Ppn01 = r1.w; Ppn02 = r2.x; Ppn11 = r2.y; Ppn12 = r2.z; Ppn22 = r2.w;
        if (c == NCH - 1) {  // exact top-of-sequence state; only last chunk owns slot T-1
            int tj = g_tj[TT - 1];
            if (tj >= 0) { out[tj] = ms0 + mc; out[M + tj] = fmaxf(Ps00, 0.0f); }
        }
    }

    // register double-buffer prefetch
    int n0 = kinit - 1;
    float4 p0 = g_rec[ridx(0, n0)], p1 = g_rec[ridx(1, n0)], p2 = g_rec[ridx(2, n0)];
    float4 p3 = g_rec[ridx(3, n0)], p4 = g_rec[ridx(4, n0)], p5 = g_rec[ridx(5, n0)];
    float4 p6 = g_rec[ridx(6, n0)];

    for (int n = n0; n >= s; --n) {
        float4 c0 = p0, c1 = p1, c2 = p2, c3 = p3, c4 = p4, c5 = p5, c6 = p6;
        if (n > s) {
            int q = n - 1;
            p0 = g_rec[ridx(0, q)]; p1 = g_rec[ridx(1, q)]; p2 = g_rec[ridx(2, q)];
            p3 = g_rec[ridx(3, q)]; p4 = g_rec[ridx(4, q)]; p5 = g_rec[ridx(5, q)];
            p6 = g_rec[ridx(6, q)];
        }
        float mf0 = c0.x, mf1 = c0.y, mf2 = c0.z;
        float Pf00 = c3.x, Pf01 = c3.y, Pf02 = c3.z, Pf11 = c3.w, Pf12 = c4.x, Pf22 = c4.y;
        float G00 = c5.x, G01 = c5.y, G02 = c5.z, G10 = c5.w;
        float G11 = c6.x, G12 = c6.y, G20 = c6.z, G21 = c6.w, G22 = c4.z;

        // m_s = m_f + G (m_s_next - m_pred_next)
        float dm0 = ms0 - mpn0, dm1 = ms1 - mpn1, dm2 = ms2 - mpn2;
        float nm0 = mf0 + G00 * dm0 + G01 * dm1 + G02 * dm2;
        float nm1 = mf1 + G10 * dm0 + G11 * dm1 + G12 * dm2;
        float nm2 = mf2 + G20 * dm0 + G21 * dm1 + G22 * dm2;

        // P_s = P_f + G (P_s_next - P_pred_next) G^T
        float D00 = Ps00 - Ppn00, D01 = Ps01 - Ppn01, D02 = Ps02 - Ppn02;
        float D11 = Ps11 - Ppn11, D12 = Ps12 - Ppn12, D22 = Ps22 - Ppn22;
        float T00 = G00 * D00 + G01 * D01 + G02 * D02;
        float T01 = G00 * D01 + G01 * D11 + G02 * D12;
        float T02 = G00 * D02 + G01 * D12 + G02 * D22;
        float T10 = G10 * D00 + G11 * D01 + G12 * D02;
        float T11 = G10 * D01 + G11 * D11 + G12 * D12;
        float T12 = G10 * D02 + G11 * D12 + G12 * D22;
        float T20 = G20 * D00 + G21 * D01 + G22 * D02;
        float T21 = G20 * D01 + G21 * D11 + G22 * D12;
        float T22 = G20 * D02 + G21 * D12 + G22 * D22;
        Ps00 = Pf00 + T00 * G00 + T01 * G01 + T02 * G02;
        Ps01 = Pf01 + T00 * G10 + T01 * G11 + T02 * G12;
        Ps02 = Pf02 + T00 * G20 + T01 * G21 + T02 * G22;
        Ps11 = Pf11 + T10 * G10 + T11 * G11 + T12 * G12;
        Ps12 = Pf12 + T10 * G20 + T11 * G21 + T12 * G22;
        Ps22 = Pf22 + T20 * G20 + T21 * G21 + T22 * G22;
        ms0 = nm0; ms1 = nm1; ms2 = nm2;

        if (n < e) {  // payload region only
            int tj = g_tj[n];
            if (tj >= 0) { out[tj] = ms0 + mc; out[M + tj] = fmaxf(Ps00, 0.0f); }
        }

        // this slot's (m_pred, P_pred) become "next" for n-1
        mpn0 = c0.w; mpn1 = c1.x; mpn2 = c1.y;
        Ppn00 = c1.z; Ppn01 = c1.w; Ppn02 = c2.x; Ppn11 = c2.y; Ppn12 = c2.z; Ppn22 = c2.w;
    }
}

extern "C" void kernel_launch(void* const* d_in, const int* in_sizes, int n_in,
                              void* d_out, int out_size) {
    const float* times = (const float*)d_in[0];
    const float* tstar = (const float*)d_in[1];
    const float* n1    = (const float*)d_in[2];
    const float* n2    = (const float*)d_in[3];
    const float* pvar  = (const float*)d_in[4];
    const float* pls   = (const float*)d_in[5];
    const float* pmc   = (const float*)d_in[6];
    int N = in_sizes[0];
    int M = in_sizes[1];
    int total = N + M;

    merge_kernel<<<(total + 255) / 256, 256>>>(times, tstar, n1, n2, pmc, N, M);
    forward_kernel<<<(NCH + 31) / 32, 32>>>(pvar, pls);
    backward_kernel<<<(NCH + 31) / 32, 32>>>(pmc, (float*)d_out, M);
}